// round 12
// baseline (speedup 1.0000x reference)
#include <cuda_runtime.h>
#include <math.h>

#define D       65536
#define BATCH   64
#define TC      10
#define NROWS_T 128
#define NROWS_S 640
#define CHUNK   2048
#define NCHUNK  32
#define INV_TS  10.0f
#define INV_TT  25.0f
#define TSHIFT  140.0f                       // fixed shift: negligible terms underflow harmlessly
#define LOG2E_TS 14.4269504088896340736f     // 10 * log2(e)
#define K1_BLOCKS 1024
#define K2_BLOCKS 512
#define F_BLOCKS  64                         // == BATCH

typedef unsigned long long u64;

// ---------------- scratch ----------------
__device__ float    g_zpart[K1_BLOCKS];      // eighth-row teacher Z partials
__device__ float    g_tinvZ[NROWS_T];
__device__ float    g_nc[D];
__device__ float    g_scpart[K2_BLOCKS];
__device__ float    g_z[NROWS_S * NCHUNK];   // [row][chunk] student Z partials
__device__ float2   g_dab[BATCH * NCHUNK];   // per (b,chunk): {A0S, A1S} raw dot sums
__device__ float    g_Y[D];                  // weighted student column sum (memset each launch)
__device__ float4   g_fin[F_BLOCKS];         // per-F-block {V, W, DA, NCY}
__device__ unsigned g_fsync;                 // monotonic counter (replay-safe)

// ---------------- helpers ----------------
__device__ __forceinline__ float warpSum(float v) {
#pragma unroll
    for (int o = 16; o > 0; o >>= 1) v += __shfl_xor_sync(0xffffffffu, v, o);
    return v;
}
__device__ __forceinline__ u64 pack2(float lo, float hi) {
    u64 r; asm("mov.b64 %0, {%1, %2};" : "=l"(r) : "f"(lo), "f"(hi)); return r;
}
__device__ __forceinline__ void unpack2(u64 p, float& lo, float& hi) {
    asm("mov.b64 {%0, %1}, %2;" : "=f"(lo), "=f"(hi) : "l"(p));
}
__device__ __forceinline__ u64 fma2(u64 a, u64 b, u64 c) {
    u64 d; asm("fma.rn.f32x2 %0, %1, %2, %3;" : "=l"(d) : "l"(a), "l"(b), "l"(c)); return d;
}
__device__ __forceinline__ u64 mul2(u64 a, u64 b) {
    u64 d; asm("mul.rn.f32x2 %0, %1, %2;" : "=l"(d) : "l"(a), "l"(b)); return d;
}
__device__ __forceinline__ u64 add2(u64 a, u64 b) {
    u64 d; asm("add.rn.f32x2 %0, %1, %2;" : "=l"(d) : "l"(a), "l"(b)); return d;
}
__device__ __forceinline__ float ex2f(float x) {
    float r; asm("ex2.approx.f32 %0, %1;" : "=f"(r) : "f"(x)); return r;
}

// ---------------- K3: streaming student pass — NO dependency on K1/K2 ----------------
// grid = (NCHUNK, BATCH), block = 256. Teacher exps from raw input (fixed shift);
// invZ deferred to finalize (A0S/A1S stored raw). Center dot replaced by
// per-element weighted column sum Y (red.add). zt in registers (R8-proven).
__global__ __launch_bounds__(256) void student_kernel(const float* __restrict__ stud,
                                                      const float* __restrict__ teach) {
    __shared__ float sz[TC][8];
    __shared__ float sab[8][2];
    const int tid = threadIdx.x, lane = tid & 31, warp = tid >> 5;
    const int chunk = blockIdx.x, b = blockIdx.y;
    const size_t coff4 = (size_t)chunk * (CHUNK / 4);
    const int i0 = tid, i1 = tid + 256;

    const float4* t0p = reinterpret_cast<const float4*>(teach + (size_t)(b * 2 + 0) * D) + coff4;
    const float4* t1p = reinterpret_cast<const float4*>(teach + (size_t)(b * 2 + 1) * D) + coff4;

    float4 ta0 = __ldg(t0p + i0), tb0 = __ldg(t0p + i1);
    float4 ta1 = __ldg(t1p + i0), tb1 = __ldg(t1p + i1);

    // UNNORMALIZED teacher exps (invZ applied in finalize)
    u64 ep0[4], ep1[4];
    ep0[0] = pack2(__expf(ta0.x * INV_TT - TSHIFT), __expf(ta0.y * INV_TT - TSHIFT));
    ep0[1] = pack2(__expf(ta0.z * INV_TT - TSHIFT), __expf(ta0.w * INV_TT - TSHIFT));
    ep0[2] = pack2(__expf(tb0.x * INV_TT - TSHIFT), __expf(tb0.y * INV_TT - TSHIFT));
    ep0[3] = pack2(__expf(tb0.z * INV_TT - TSHIFT), __expf(tb0.w * INV_TT - TSHIFT));
    ep1[0] = pack2(__expf(ta1.x * INV_TT - TSHIFT), __expf(ta1.y * INV_TT - TSHIFT));
    ep1[1] = pack2(__expf(ta1.z * INV_TT - TSHIFT), __expf(ta1.w * INV_TT - TSHIFT));
    ep1[2] = pack2(__expf(tb1.x * INV_TT - TSHIFT), __expf(tb1.y * INV_TT - TSHIFT));
    ep1[3] = pack2(__expf(tb1.z * INV_TT - TSHIFT), __expf(tb1.w * INV_TT - TSHIFT));

    const u64 KTS  = pack2(LOG2E_TS, LOG2E_TS);
    const u64 TWO2 = pack2(2.0f, 2.0f);

    const ulonglong2* xbase = reinterpret_cast<const ulonglong2*>(stud + (size_t)(b * TC) * D + (size_t)chunk * CHUNK);
    ulonglong2 xa = __ldcs(xbase + i0);
    ulonglong2 xb = __ldcs(xbase + i1);

    float zt[TC];
    u64 A0S = 0ull, A1S = 0ull;
    u64 Y0 = 0ull, Y1 = 0ull, Y2 = 0ull, Y3 = 0ull;   // per-element weighted sums

#pragma unroll
    for (int t = 0; t < TC; t++) {
        ulonglong2 xan, xbn;
        if (t < TC - 1) {
            const ulonglong2* xn = xbase + (size_t)(t + 1) * (D / 4);
            xan = __ldcs(xn + i0);
            xbn = __ldcs(xn + i1);
        }

        u64 A0 = 0ull, A1 = 0ull;
        A0 = fma2(ep0[0], xa.x, A0); A1 = fma2(ep1[0], xa.x, A1);
        A0 = fma2(ep0[1], xa.y, A0); A1 = fma2(ep1[1], xa.y, A1);
        A0 = fma2(ep0[2], xb.x, A0); A1 = fma2(ep1[2], xb.x, A1);
        A0 = fma2(ep0[3], xb.y, A0); A1 = fma2(ep1[3], xb.y, A1);

        // weight folds (compile-time per unrolled t): t==0: w0=0,w1=1; t==1: w0=1,w1=0; t>=2: both
        if (t == 0)      { A1S = add2(A1S, A1); }
        else if (t == 1) { A0S = add2(A0S, A0); }
        else             { A0S = add2(A0S, A0); A1S = add2(A1S, A1); }

        // Y += wc_t * x  (wc=1 for t<2, 2 for t>=2)
        if (t < 2) {
            Y0 = add2(Y0, xa.x); Y1 = add2(Y1, xa.y);
            Y2 = add2(Y2, xb.x); Y3 = add2(Y3, xb.y);
        } else {
            Y0 = fma2(xa.x, TWO2, Y0); Y1 = fma2(xa.y, TWO2, Y1);
            Y2 = fma2(xb.x, TWO2, Y2); Y3 = fma2(xb.y, TWO2, Y3);
        }

        u64 q0 = mul2(xa.x, KTS), q1 = mul2(xa.y, KTS), q2 = mul2(xb.x, KTS), q3 = mul2(xb.y, KTS);
        float f0, f1, f2, f3, f4, f5, f6, f7;
        unpack2(q0, f0, f1); unpack2(q1, f2, f3);
        unpack2(q2, f4, f5); unpack2(q3, f6, f7);
        zt[t] = ((ex2f(f0) + ex2f(f1)) + (ex2f(f2) + ex2f(f3)))
              + ((ex2f(f4) + ex2f(f5)) + (ex2f(f6) + ex2f(f7)));

        xa = xan;
        xb = xbn;
    }

    // publish Y via red.add (64-way collisions per address; issue cost ~8x2cyc/thread)
    {
        float* yb = g_Y + (size_t)chunk * CHUNK;
        float a, c;
        unpack2(Y0, a, c); atomicAdd(yb + 4 * i0 + 0, a); atomicAdd(yb + 4 * i0 + 1, c);
        unpack2(Y1, a, c); atomicAdd(yb + 4 * i0 + 2, a); atomicAdd(yb + 4 * i0 + 3, c);
        unpack2(Y2, a, c); atomicAdd(yb + 4 * i1 + 0, a); atomicAdd(yb + 4 * i1 + 1, c);
        unpack2(Y3, a, c); atomicAdd(yb + 4 * i1 + 2, a); atomicAdd(yb + 4 * i1 + 3, c);
    }

    // A0S/A1S reduction
    {
        float lo, hi, a0, a1;
        unpack2(A0S, lo, hi); a0 = warpSum(lo + hi);
        unpack2(A1S, lo, hi); a1 = warpSum(lo + hi);
        if (lane == 0) { sab[warp][0] = a0; sab[warp][1] = a1; }
    }
    // zt reductions (registers, R8-style)
#pragma unroll
    for (int t = 0; t < TC; t++) {
        float z = warpSum(zt[t]);
        if (lane == 0) sz[t][warp] = z;
    }
    __syncthreads();
    if (tid < TC) {
        float Z = 0.0f;
#pragma unroll
        for (int i = 0; i < 8; i++) Z += sz[tid][i];
        g_z[(b * TC + tid) * NCHUNK + chunk] = Z;
    } else if (tid == 32) {
        float a0 = 0, a1 = 0;
#pragma unroll
        for (int i = 0; i < 8; i++) { a0 += sab[i][0]; a1 += sab[i][1]; }
        float2 o = {a0, a1};
        g_dab[b * NCHUNK + chunk] = o;
    }
}

// ---------------- K1: teacher Z eighth-row partials (L2-hot after K3) ----------------
// grid = 1024, block = 256; row = blk>>3
__global__ __launch_bounds__(256) void teacher_z_kernel(const float* __restrict__ teach) {
    const int blk = blockIdx.x, tid = threadIdx.x;
    const float4* src = reinterpret_cast<const float4*>(teach) + (size_t)blk * (D / 32);
    __shared__ float sz[8];

    float z = 0.0f;
#pragma unroll
    for (int k = 0; k < 8; k++) {
        float4 v = __ldg(src + tid + k * 256);
        z += __expf(v.x * INV_TT - TSHIFT) + __expf(v.y * INV_TT - TSHIFT)
           + __expf(v.z * INV_TT - TSHIFT) + __expf(v.w * INV_TT - TSHIFT);
    }
    z = warpSum(z);
    if ((tid & 31) == 0) sz[tid >> 5] = z;
    __syncthreads();
    if (tid == 0) {
        float Z = 0.0f;
#pragma unroll
        for (int i = 0; i < 8; i++) Z += sz[i];
        g_zpart[blk] = Z;
    }
}

// ---------------- K2: new_center + S_c partials + publish invZ ----------------
// grid = 512, block = 256; 32 float4 columns per block, teacher re-read L2-hot
__global__ __launch_bounds__(256) void center_kernel(const float* __restrict__ teach,
                                                     const float* __restrict__ center) {
    __shared__ float sW[NROWS_T];
    __shared__ float4 sacc[8][32];
    const int tid = threadIdx.x, lane = tid & 31;
    const int blk = blockIdx.x;

    if (tid < NROWS_T) {
        float Z = 0.0f;
#pragma unroll
        for (int i = 0; i < 8; i++) Z += g_zpart[tid * 8 + i];
        float w = 1.0f / Z;
        sW[tid] = w;
        if (blk == 0) g_tinvZ[tid] = w;
    }
    __syncthreads();

    const int g = tid >> 5, c = lane;            // 8 row-groups x 32 columns
    const int c4 = blk * 32 + c;                 // 0..16383
    const float4* tp = reinterpret_cast<const float4*>(teach);

    float4 acc = {0, 0, 0, 0};
#pragma unroll
    for (int rr = 0; rr < 16; rr++) {
        const int r = g * 16 + rr;
        float4 v = __ldg(tp + (size_t)r * (D / 4) + c4);
        float w = sW[r];
        acc.x += __expf(v.x * INV_TT - TSHIFT) * w;
        acc.y += __expf(v.y * INV_TT - TSHIFT) * w;
        acc.z += __expf(v.z * INV_TT - TSHIFT) * w;
        acc.w += __expf(v.w * INV_TT - TSHIFT) * w;
    }
    sacc[g][c] = acc;
    __syncthreads();

    if (tid < 32) {
        float4 A = {0, 0, 0, 0};
#pragma unroll
        for (int i = 0; i < 8; i++) {
            float4 p = sacc[i][tid];
            A.x += p.x; A.y += p.y; A.z += p.z; A.w += p.w;
        }
        const int cc = blk * 32 + tid;
        float4 cen = __ldg(reinterpret_cast<const float4*>(center) + cc);
        const float mom = 0.9f, sc = 0.1f / 128.0f;
        float4 nc;
        nc.x = mom * cen.x + sc * A.x;
        nc.y = mom * cen.y + sc * A.y;
        nc.z = mom * cen.z + sc * A.z;
        nc.w = mom * cen.w + sc * A.w;
        reinterpret_cast<float4*>(g_nc)[cc] = nc;

        float s = (nc.x + nc.y) + (nc.z + nc.w);
        s = warpSum(s);
        if (tid == 0) g_scpart[blk] = s;
    }
}

// ---------------- F: lse + invZ-application + dot(nc,Y) + last-block combine ----------------
// grid = 64 (== BATCH), block = 320. Block blk: 10 rows (b=blk), dab slice, 1024-elem nc.Y slice.
// total = INV_TS*(NCY - DA) - S_c*V + W, over 1152.
__global__ __launch_bounds__(320) void finalize_kernel(float* __restrict__ out) {
    __shared__ float sv[10], sw_[10], sda, sncy[10];
    __shared__ int   slast;
    __shared__ float sfin[2][4];
    const int tid = threadIdx.x, lane = tid & 31, w = tid >> 5;
    const int blk = blockIdx.x;
    const int r = blk * 10 + w;

    // per-row lse
    float Z = warpSum(g_z[r * NCHUNK + lane]);
    if (lane == 0) {
        float lse = __logf(Z);
        int t = r % TC;
        sv[w]  = lse * ((t >= 2) ? 2.0f : 1.0f);
        sw_[w] = lse * ((t < 2) ? 1.0f : 2.0f);
    }
    // DA for b = blk: sum over chunks, apply invZ
    if (w == 0) {
        float2 q = g_dab[blk * NCHUNK + lane];
        float a0 = warpSum(q.x);
        float a1 = warpSum(q.y);
        if (lane == 0) sda = a0 * g_tinvZ[2 * blk] + a1 * g_tinvZ[2 * blk + 1];
    }
    // NCY slice: dot(nc, Y) over [blk*1024, blk*1024+1024)
    {
        float ncy = 0.0f;
        for (int i = tid; i < 1024; i += 320)
            ncy += g_nc[blk * 1024 + i] * g_Y[blk * 1024 + i];
        ncy = warpSum(ncy);
        if (lane == 0) sncy[w] = ncy;
    }
    __syncthreads();
    if (tid == 0) {
        float V = 0, W = 0, NCY = 0;
#pragma unroll
        for (int i = 0; i < 10; i++) { V += sv[i]; W += sw_[i]; NCY += sncy[i]; }
        float4 o = {V, W, sda, NCY};
        g_fin[blk] = o;
        __threadfence();
        unsigned old = atomicAdd(&g_fsync, 1u);     // monotonic: replay-safe
        slast = ((old + 1u) % F_BLOCKS == 0u) ? 1 : 0;
    }
    __syncthreads();
    if (!slast) return;

    // ---- fused final combine ----
    __threadfence();
    float V = 0, W = 0, DA = 0, NCY = 0, s = 0;
    if (tid < F_BLOCKS) {
        float4 f = *(const float4*)__builtin_assume_aligned(&g_fin[tid], 16);
        float4 q = { __ldcg(&g_fin[tid].x), __ldcg(&g_fin[tid].y),
                     __ldcg(&g_fin[tid].z), __ldcg(&g_fin[tid].w) };
        (void)f;
        V = q.x; W = q.y; DA = q.z; NCY = q.w;
    }
    if (tid < 256) s = __ldcg(&g_scpart[tid]) + __ldcg(&g_scpart[tid + 256]);

    V = warpSum(V); W = warpSum(W); DA = warpSum(DA); NCY = warpSum(NCY); s = warpSum(s);
    if (lane == 0 && w < 2) { sfin[w][0] = V; sfin[w][1] = W; sfin[w][2] = DA; sfin[w][3] = NCY; }
    __shared__ float ssc[10];
    if (lane == 0) ssc[w] = s;
    __syncthreads();
    if (tid == 0) {
        float Vf = sfin[0][0] + sfin[1][0];
        float Wf = sfin[0][1] + sfin[1][1];
        float Df = sfin[0][2] + sfin[1][2];
        float Nf = sfin[0][3] + sfin[1][3];
        float Sc = 0;
#pragma unroll
        for (int i = 0; i < 10; i++) Sc += ssc[i];
        out[0] = (INV_TS * (Nf - Df) - Sc * Vf + Wf) / (float)(BATCH * 2 * (TC - 1));   // /1152
    }
}

// ---------------- launch ----------------
extern "C" void kernel_launch(void* const* d_in, const int* in_sizes, int n_in,
                              void* d_out, int out_size) {
    const float* stud  = nullptr;
    const float* teach = nullptr;
    const float* cen   = nullptr;
    for (int i = 0; i < n_in; i++) {
        if      (in_sizes[i] == NROWS_S * D) stud  = (const float*)d_in[i];
        else if (in_sizes[i] == NROWS_T * D) teach = (const float*)d_in[i];
        else if (in_sizes[i] == D)           cen   = (const float*)d_in[i];
    }

    void* yptr = nullptr;
    cudaGetSymbolAddress(&yptr, g_Y);
    cudaMemsetAsync(yptr, 0, D * sizeof(float));

    student_kernel<<<dim3(NCHUNK, BATCH), 256>>>(stud, teach);   // no K1/K2 dependency
    teacher_z_kernel<<<K1_BLOCKS, 256>>>(teach);                 // teacher now L2-hot
    center_kernel<<<K2_BLOCKS, 256>>>(teach, cen);
    finalize_kernel<<<F_BLOCKS, 320>>>((float*)d_out);
}

// round 13
// speedup vs baseline: 1.1396x; 1.1396x over previous
#include <cuda_runtime.h>
#include <math.h>

#define D       65536
#define BATCH   64
#define TC      10
#define NROWS_T 128
#define NROWS_S 640
#define CHUNK   2048
#define NCHUNK  32
#define INV_TS  10.0f
#define INV_TT  25.0f
#define TSHIFT  140.0f                       // fixed shift: 25*x <= ~137 for N(0,1)
#define LOG2E_TS 14.4269504088896340736f     // 10 * log2(e)
#define K1_BLOCKS 1024
#define K2_BLOCKS 512
#define F_BLOCKS  64

typedef unsigned long long u64;

// ---------------- scratch ----------------
__device__ float    g_zpart[K1_BLOCKS];      // eighth-row teacher Z partials
__device__ float    g_tinvZ[NROWS_T];
__device__ float    g_nc[D];
__device__ float    g_scpart[K2_BLOCKS];
__device__ float    g_z[NROWS_S * NCHUNK];   // [row][chunk] student Z partials
__device__ float    g_ds[NCHUNK * BATCH];    // per-K3-block folded dot sums
__device__ float    g_fin[F_BLOCKS * 3];     // per-F-block {V, W, DS}
__device__ unsigned g_fsync;                 // monotonic counter (replay-safe)

// ---------------- helpers ----------------
__device__ __forceinline__ float warpSum(float v) {
#pragma unroll
    for (int o = 16; o > 0; o >>= 1) v += __shfl_xor_sync(0xffffffffu, v, o);
    return v;
}
__device__ __forceinline__ u64 pack2(float lo, float hi) {
    u64 r; asm("mov.b64 %0, {%1, %2};" : "=l"(r) : "f"(lo), "f"(hi)); return r;
}
__device__ __forceinline__ void unpack2(u64 p, float& lo, float& hi) {
    asm("mov.b64 {%0, %1}, %2;" : "=f"(lo), "=f"(hi) : "l"(p));
}
__device__ __forceinline__ u64 fma2(u64 a, u64 b, u64 c) {
    u64 d; asm("fma.rn.f32x2 %0, %1, %2, %3;" : "=l"(d) : "l"(a), "l"(b), "l"(c)); return d;
}
__device__ __forceinline__ u64 mul2(u64 a, u64 b) {
    u64 d; asm("mul.rn.f32x2 %0, %1, %2;" : "=l"(d) : "l"(a), "l"(b)); return d;
}
__device__ __forceinline__ u64 add2(u64 a, u64 b) {
    u64 d; asm("add.rn.f32x2 %0, %1, %2;" : "=l"(d) : "l"(a), "l"(b)); return d;
}
__device__ __forceinline__ float ex2f(float x) {
    float r; asm("ex2.approx.f32 %0, %1;" : "=f"(r) : "f"(x)); return r;
}

// ---------------- K1: teacher Z eighth-row partials ----------------
// grid = 1024, block = 256; row = blk>>3  (R8 verbatim)
__global__ __launch_bounds__(256) void teacher_z_kernel(const float* __restrict__ teach) {
    const int blk = blockIdx.x, tid = threadIdx.x;
    const float4* src = reinterpret_cast<const float4*>(teach) + (size_t)blk * (D / 32);
    __shared__ float sz[8];

    float z = 0.0f;
#pragma unroll
    for (int k = 0; k < 8; k++) {
        float4 v = __ldg(src + tid + k * 256);
        z += __expf(v.x * INV_TT - TSHIFT) + __expf(v.y * INV_TT - TSHIFT)
           + __expf(v.z * INV_TT - TSHIFT) + __expf(v.w * INV_TT - TSHIFT);
    }
    z = warpSum(z);
    if ((tid & 31) == 0) sz[tid >> 5] = z;
    __syncthreads();
    if (tid == 0) {
        float Z = 0.0f;
#pragma unroll
        for (int i = 0; i < 8; i++) Z += sz[i];
        g_zpart[blk] = Z;
    }
}

// ---------------- K2: new_center + S_c partials + publish invZ ----------------
// grid = 512, block = 256  (R8 verbatim)
__global__ __launch_bounds__(256) void center_kernel(const float* __restrict__ teach,
                                                     const float* __restrict__ center) {
    __shared__ float sW[NROWS_T];
    __shared__ float4 sacc[8][32];
    const int tid = threadIdx.x, lane = tid & 31;
    const int blk = blockIdx.x;

    if (tid < NROWS_T) {
        float Z = 0.0f;
#pragma unroll
        for (int i = 0; i < 8; i++) Z += g_zpart[tid * 8 + i];
        float w = 1.0f / Z;
        sW[tid] = w;
        if (blk == 0) g_tinvZ[tid] = w;
    }
    __syncthreads();

    const int g = tid >> 5, c = lane;            // 8 row-groups x 32 columns
    const int c4 = blk * 32 + c;                 // 0..16383
    const float4* tp = reinterpret_cast<const float4*>(teach);

    float4 acc = {0, 0, 0, 0};
#pragma unroll
    for (int rr = 0; rr < 16; rr++) {
        const int r = g * 16 + rr;
        float4 v = __ldg(tp + (size_t)r * (D / 4) + c4);
        float w = sW[r];
        acc.x += __expf(v.x * INV_TT - TSHIFT) * w;
        acc.y += __expf(v.y * INV_TT - TSHIFT) * w;
        acc.z += __expf(v.z * INV_TT - TSHIFT) * w;
        acc.w += __expf(v.w * INV_TT - TSHIFT) * w;
    }
    sacc[g][c] = acc;
    __syncthreads();

    if (tid < 32) {
        float4 A = {0, 0, 0, 0};
#pragma unroll
        for (int i = 0; i < 8; i++) {
            float4 p = sacc[i][tid];
            A.x += p.x; A.y += p.y; A.z += p.z; A.w += p.w;
        }
        const int cc = blk * 32 + tid;
        float4 cen = __ldg(reinterpret_cast<const float4*>(center) + cc);
        const float mom = 0.9f, sc = 0.1f / 128.0f;
        float4 nc;
        nc.x = mom * cen.x + sc * A.x;
        nc.y = mom * cen.y + sc * A.y;
        nc.z = mom * cen.z + sc * A.z;
        nc.w = mom * cen.w + sc * A.w;
        reinterpret_cast<float4*>(g_nc)[cc] = nc;

        float s = (nc.x + nc.y) + (nc.z + nc.w);
        s = warpSum(s);
        if (tid == 0) g_scpart[blk] = s;
    }
}

// ---------------- K3: streaming student pass (R8 verbatim) ----------------
// grid = (NCHUNK, BATCH), block = 256. DSUM folded across all 10 crops in one
// packed accumulator; per-crop z in registers, reduced once after the loop.
__global__ __launch_bounds__(256) void student_kernel(const float* __restrict__ stud,
                                                      const float* __restrict__ teach) {
    __shared__ float sz[TC][8];
    __shared__ float sds[8];
    const int tid = threadIdx.x, lane = tid & 31, warp = tid >> 5;
    const int chunk = blockIdx.x, b = blockIdx.y;
    const size_t coff4 = (size_t)chunk * (CHUNK / 4);
    const int i0 = tid, i1 = tid + 256;

    const float4* t0p = reinterpret_cast<const float4*>(teach + (size_t)(b * 2 + 0) * D) + coff4;
    const float4* t1p = reinterpret_cast<const float4*>(teach + (size_t)(b * 2 + 1) * D) + coff4;
    const ulonglong2* ncp = reinterpret_cast<const ulonglong2*>(g_nc + (size_t)chunk * CHUNK);

    const float iZ0 = g_tinvZ[b * 2 + 0], iZ1 = g_tinvZ[b * 2 + 1];

    float4 ta0 = __ldg(t0p + i0), tb0 = __ldg(t0p + i1);
    float4 ta1 = __ldg(t1p + i0), tb1 = __ldg(t1p + i1);
    ulonglong2 nA = __ldg(ncp + i0), nB = __ldg(ncp + i1);

    // UNNORMALIZED teacher exps (invZ folded into PK constants below)
    u64 ep0[4], ep1[4], nck[4];
    ep0[0] = pack2(__expf(ta0.x * INV_TT - TSHIFT), __expf(ta0.y * INV_TT - TSHIFT));
    ep0[1] = pack2(__expf(ta0.z * INV_TT - TSHIFT), __expf(ta0.w * INV_TT - TSHIFT));
    ep0[2] = pack2(__expf(tb0.x * INV_TT - TSHIFT), __expf(tb0.y * INV_TT - TSHIFT));
    ep0[3] = pack2(__expf(tb0.z * INV_TT - TSHIFT), __expf(tb0.w * INV_TT - TSHIFT));
    ep1[0] = pack2(__expf(ta1.x * INV_TT - TSHIFT), __expf(ta1.y * INV_TT - TSHIFT));
    ep1[1] = pack2(__expf(ta1.z * INV_TT - TSHIFT), __expf(ta1.w * INV_TT - TSHIFT));
    ep1[2] = pack2(__expf(tb1.x * INV_TT - TSHIFT), __expf(tb1.y * INV_TT - TSHIFT));
    ep1[3] = pack2(__expf(tb1.z * INV_TT - TSHIFT), __expf(tb1.w * INV_TT - TSHIFT));
    nck[0] = nA.x; nck[1] = nA.y; nck[2] = nB.x; nck[3] = nB.y;

    const u64 KTS  = pack2(LOG2E_TS, LOG2E_TS);
    const u64 PK0n = pack2(-iZ0, -iZ0);
    const u64 PK1n = pack2(-iZ1, -iZ1);
    const u64 TWO2 = pack2(2.0f, 2.0f);

    const ulonglong2* xbase = reinterpret_cast<const ulonglong2*>(stud + (size_t)(b * TC) * D + (size_t)chunk * CHUNK);
    ulonglong2 xa = __ldcs(xbase + i0);
    ulonglong2 xb = __ldcs(xbase + i1);

    float zt[TC];
    u64 DSUM = 0ull;

#pragma unroll
    for (int t = 0; t < TC; t++) {
        ulonglong2 xan, xbn;
        if (t < TC - 1) {
            const ulonglong2* xn = xbase + (size_t)(t + 1) * (D / 4);
            xan = __ldcs(xn + i0);
            xbn = __ldcs(xn + i1);
        }

        u64 A0 = 0ull, A1 = 0ull, AC = 0ull;
        A0 = fma2(ep0[0], xa.x, A0); A1 = fma2(ep1[0], xa.x, A1); AC = fma2(nck[0], xa.x, AC);
        A0 = fma2(ep0[1], xa.y, A0); A1 = fma2(ep1[1], xa.y, A1); AC = fma2(nck[1], xa.y, AC);
        A0 = fma2(ep0[2], xb.x, A0); A1 = fma2(ep1[2], xb.x, A1); AC = fma2(nck[2], xb.x, AC);
        A0 = fma2(ep0[3], xb.y, A0); A1 = fma2(ep1[3], xb.y, A1); AC = fma2(nck[3], xb.y, AC);

        if (t == 0) {
            DSUM = fma2(A1, PK1n, DSUM);
            DSUM = add2(DSUM, AC);
        } else if (t == 1) {
            DSUM = fma2(A0, PK0n, DSUM);
            DSUM = add2(DSUM, AC);
        } else {
            DSUM = fma2(A0, PK0n, DSUM);
            DSUM = fma2(A1, PK1n, DSUM);
            DSUM = fma2(AC, TWO2, DSUM);
        }

        u64 q0 = mul2(xa.x, KTS), q1 = mul2(xa.y, KTS), q2 = mul2(xb.x, KTS), q3 = mul2(xb.y, KTS);
        float f0, f1, f2, f3, f4, f5, f6, f7;
        unpack2(q0, f0, f1); unpack2(q1, f2, f3);
        unpack2(q2, f4, f5); unpack2(q3, f6, f7);
        zt[t] = ((ex2f(f0) + ex2f(f1)) + (ex2f(f2) + ex2f(f3)))
              + ((ex2f(f4) + ex2f(f5)) + (ex2f(f6) + ex2f(f7)));

        xa = xan;
        xb = xbn;
    }

    // deferred reductions (once per block)
#pragma unroll
    for (int t = 0; t < TC; t++) {
        float z = warpSum(zt[t]);
        if (lane == 0) sz[t][warp] = z;
    }
    {
        float lo, hi;
        unpack2(DSUM, lo, hi);
        float ds = warpSum(lo + hi);
        if (lane == 0) sds[warp] = ds;
    }
    __syncthreads();
    if (tid < TC) {
        float Z = 0.0f;
#pragma unroll
        for (int i = 0; i < 8; i++) Z += sz[tid][i];
        g_z[(b * TC + tid) * NCHUNK + chunk] = Z;
    } else if (tid == 32) {
        float DS = 0.0f;
#pragma unroll
        for (int i = 0; i < 8; i++) DS += sds[i];
        g_ds[b * NCHUNK + chunk] = DS;
    }
}

// ---------------- F: warp-per-row lse + dsum slices + fused last-block combine ----------------
// grid = 64, block = 320  (R8 verbatim)
__global__ __launch_bounds__(320) void finalize_kernel(float* __restrict__ out) {
    __shared__ float sv[10], sw_[10], sds1;
    __shared__ int   slast;
    __shared__ float sfin[10][4];
    const int tid = threadIdx.x, lane = tid & 31, w = tid >> 5;
    const int blk = blockIdx.x;
    const int r = blk * 10 + w;

    float Z = warpSum(g_z[r * NCHUNK + lane]);
    if (lane == 0) {
        float lse = __logf(Z);
        int t = r % TC;
        float wc = (t >= 2) ? 2.0f : 1.0f;
        float wp = (t < 2) ? 1.0f : 2.0f;     // w0 + w1
        sv[w]  = lse * wc;
        sw_[w] = lse * wp;
    }
    if (w == 0) {
        float ds = warpSum(g_ds[blk * 32 + lane]);
        if (lane == 0) sds1 = ds;
    }
    __syncthreads();
    if (tid == 0) {
        float V = 0, W = 0;
#pragma unroll
        for (int i = 0; i < 10; i++) { V += sv[i]; W += sw_[i]; }
        g_fin[blk * 3 + 0] = V;
        g_fin[blk * 3 + 1] = W;
        g_fin[blk * 3 + 2] = sds1;
        __threadfence();
        unsigned old = atomicAdd(&g_fsync, 1u);     // monotonic: replay-safe
        slast = ((old + 1u) % F_BLOCKS == 0u) ? 1 : 0;
    }
    __syncthreads();
    if (!slast) return;

    // ---- fused final combine ----
    __threadfence();
    float V = 0, W = 0, DS = 0, s = 0;
    if (tid < F_BLOCKS) {
        V  = __ldcg(&g_fin[tid * 3 + 0]);
        W  = __ldcg(&g_fin[tid * 3 + 1]);
        DS = __ldcg(&g_fin[tid * 3 + 2]);
    }
    if (tid < 256) s = __ldcg(&g_scpart[tid]) + __ldcg(&g_scpart[tid + 256]);

    V = warpSum(V); W = warpSum(W); DS = warpSum(DS); s = warpSum(s);
    if (lane == 0) { sfin[w][0] = V; sfin[w][1] = W; sfin[w][2] = DS; sfin[w][3] = s; }
    __syncthreads();
    if (tid == 0) {
        float Vf = 0, Wf = 0, Df = 0, Sc = 0;
#pragma unroll
        for (int i = 0; i < 10; i++) { Vf += sfin[i][0]; Wf += sfin[i][1]; Df += sfin[i][2]; Sc += sfin[i][3]; }
        out[0] = (INV_TS * Df - Sc * Vf + Wf) / (float)(BATCH * 2 * (TC - 1));   // /1152
    }
}

// ---------------- launch: overlap teacher pipeline with student pass ----------------
// Event fork/join (CUDA-graph legal). K1->K2 on side stream; K3 concurrent on
// main stream; finalize after join. Stream/events created per call (kernel_launch
// runs only a few times; graph replay does not re-enter it). No device allocs.
extern "C" void kernel_launch(void* const* d_in, const int* in_sizes, int n_in,
                              void* d_out, int out_size) {
    const float* stud  = nullptr;
    const float* teach = nullptr;
    const float* cen   = nullptr;
    for (int i = 0; i < n_in; i++) {
        if      (in_sizes[i] == NROWS_S * D) stud  = (const float*)d_in[i];
        else if (in_sizes[i] == NROWS_T * D) teach = (const float*)d_in[i];
        else if (in_sizes[i] == D)           cen   = (const float*)d_in[i];
    }

    cudaStream_t s2;
    cudaEvent_t evFork, evJoin;
    cudaStreamCreateWithFlags(&s2, cudaStreamNonBlocking);
    cudaEventCreateWithFlags(&evFork, cudaEventDisableTiming);
    cudaEventCreateWithFlags(&evJoin, cudaEventDisableTiming);

    cudaEventRecord(evFork, 0);                 // fork from the (captured) main stream
    cudaStreamWaitEvent(s2, evFork, 0);

    teacher_z_kernel<<<K1_BLOCKS, 256, 0, s2>>>(teach);
    center_kernel<<<K2_BLOCKS, 256, 0, s2>>>(teach, cen);
    cudaEventRecord(evJoin, s2);

    student_kernel<<<dim3(NCHUNK, BATCH), 256>>>(stud, teach);   // concurrent with s2

    cudaStreamWaitEvent(0, evJoin, 0);          // join
    finalize_kernel<<<F_BLOCKS, 320>>>((float*)d_out);

    cudaEventDestroy(evFork);
    cudaEventDestroy(evJoin);
    cudaStreamDestroy(s2);
}